// round 4
// baseline (speedup 1.0000x reference)
#include <cuda_runtime.h>
#include <math.h>

#define B_   256
#define T_   256
#define D_   512
#define H_   512
#define O_   256
#define EPS_ 1e-5f

#define G_   128       // persistent CTAs = 64 col-groups x 2 batch-halves
#define CG_  64        // column groups
#define HC_  8         // feature columns per col-group
#define PP_  64        // batch pairs per half (128 batch elems)
#define NKG_ 8         // k-groups
#define KG_  64        // k per group
#define NT_  512       // 64 pairs x 8 k-groups
#define NW_  (NT_/32)
#define NS_  (T_ + 2)  // wavefront steps

typedef unsigned long long ull;

// ---------------- static device scratch ----------------
__device__ float d_xT[(size_t)T_ * D_ * B_];   // [t][k][i]
__device__ float d_h0 [2][H_ * B_];            // ping-pong  [k][i]
__device__ float d_hm0[2][H_ * B_];            // ping-pong
__device__ float d_hm1[H_ * B_];               // single buffer
__device__ float d_part[2][3 * CG_ * 2 * 16];  // BN partial stats [phase][cell][cg][b][16]
__device__ unsigned d_pcnt[CG_];               // partner-pair barrier counters

__device__ unsigned          g_cnt;
__device__ volatile unsigned g_gen;

// ---------------- packed f32x2 helpers ----------------
__device__ __forceinline__ ull pk2(float x, float y) {
    ull r; asm("mov.b64 %0, {%1, %2};" : "=l"(r) : "f"(x), "f"(y)); return r;
}
__device__ __forceinline__ void upk2(float& x, float& y, ull v) {
    asm("mov.b64 {%0, %1}, %2;" : "=f"(x), "=f"(y) : "l"(v));
}
__device__ __forceinline__ void fma2(ull& d, ull a, ull b) {
    asm("fma.rn.f32x2 %0, %1, %2, %0;" : "+l"(d) : "l"(a), "l"(b));
}
__device__ __forceinline__ ull ldcg64(const float* p) {
    return __ldcg((const ull*)p);
}

// ---------------- software grid barrier ----------------
__device__ __forceinline__ void gsync() {
    __syncthreads();
    if (threadIdx.x == 0) {
        __threadfence();
        unsigned my = g_gen;
        if (atomicAdd(&g_cnt, 1u) == (unsigned)(G_ - 1)) {
            g_cnt = 0u;
            __threadfence();
            g_gen = my + 1u;
        } else {
            while (g_gen == my) { __nanosleep(32); }
            __threadfence();
        }
    }
    __syncthreads();
}

// ---------------- partner stats exchange ----------------
// sred[w*16+q] holds per-warp partials for warps 0..5 (cell = w/2).
// Produces global (both halves) sums in scomb[48] = [cell][col*2+stat].
__device__ __forceinline__ void stats_exchange(int phase, unsigned tgt,
                                               int cg, int b,
                                               const float* sred, float* scomb) {
    const int tid = threadIdx.x;
    if (tid < 48) {
        int cell = tid >> 4, q = tid & 15;
        float f = sred[(2 * cell) * 16 + q] + sred[(2 * cell + 1) * 16 + q];
        scomb[tid] = f;
        __stcg(&d_part[phase][((cell * CG_ + cg) * 2 + b) * 16 + q], f);
        __threadfence();
    }
    __syncthreads();
    if (tid == 0) {
        atomicAdd(&d_pcnt[cg], 1u);
        while (__ldcg(&d_pcnt[cg]) < tgt) { __nanosleep(32); }
    }
    __syncthreads();
    if (tid < 48) {
        int cell = tid >> 4, q = tid & 15;
        scomb[tid] += __ldcg(&d_part[phase][((cell * CG_ + cg) * 2 + (1 - b)) * 16 + q]);
    }
    __syncthreads();
}

// ---------------- block allreduce (head) ----------------
__device__ __forceinline__ float block_allreduce_max(float v, float* s) {
    __syncthreads();
    #pragma unroll
    for (int off = 16; off > 0; off >>= 1)
        v = fmaxf(v, __shfl_xor_sync(0xffffffffu, v, off));
    if ((threadIdx.x & 31) == 0) s[threadIdx.x >> 5] = v;
    __syncthreads();
    float m = s[0];
    #pragma unroll
    for (int w = 1; w < NW_; w++) m = fmaxf(m, s[w]);
    return m;
}
__device__ __forceinline__ float block_allreduce_sum(float v, float* s) {
    __syncthreads();
    #pragma unroll
    for (int off = 16; off > 0; off >>= 1)
        v += __shfl_xor_sync(0xffffffffu, v, off);
    if ((threadIdx.x & 31) == 0) s[threadIdx.x >> 5] = v;
    __syncthreads();
    float r = 0.f;
    #pragma unroll
    for (int w = 0; w < NW_; w++) r += s[w];
    return r;
}

// ---------------- transpose x: [B][T][D] -> [T][D][B] ----------------
__global__ void transpose_kernel(const float* __restrict__ x) {
    __shared__ float sm[32][33];
    int t  = blockIdx.x;
    int k0 = blockIdx.y * 32;
    int i0 = blockIdx.z * 32;
    int tx = threadIdx.x, ty = threadIdx.y;
    sm[ty][tx] = x[((size_t)(i0 + ty) * T_ + t) * D_ + (k0 + tx)];
    __syncthreads();
    d_xT[((size_t)t * D_ + (k0 + ty)) * B_ + (i0 + tx)] = sm[tx][ty];
}

// dynamic smem layout sizes (in elements)
#define W0D_OFF  0
#define WMD_OFF  (HC_ * 512)
#define PEXA_OFF (2 * HC_ * 512)
#define PEXB_OFF (2 * HC_ * 512 + NKG_ * HC_ * PP_)
#define ULL_TOT  (2 * HC_ * 512 + 2 * NKG_ * HC_ * PP_)
#define SMEM_BYTES (ULL_TOT * 8 + (96 + 48 + 48 + 48) * 4)

// ---------------- persistent wavefront kernel ----------------
__global__ void __launch_bounds__(NT_, 1) rnn_kernel(
    const float* __restrict__ W0,  const float* __restrict__ b0,
    const float* __restrict__ u0,  const float* __restrict__ g10,
    const float* __restrict__ be10,const float* __restrict__ g20,
    const float* __restrict__ be20,
    const float* __restrict__ Wm,  const float* __restrict__ bm,
    const float* __restrict__ um,  const float* __restrict__ g1m,
    const float* __restrict__ be1m,const float* __restrict__ g2m,
    const float* __restrict__ be2m,
    const float* __restrict__ Wfc, const float* __restrict__ bfc,
    float* __restrict__ out) {

    extern __shared__ __align__(16) char smraw[];
    ull*   W0d  = (ull*)smraw;                 // [HC_][512] (w,w)
    ull*   Wmd  = W0d + WMD_OFF;               // [HC_][512]
    ull*   pexA = W0d + PEXA_OFF;              // cell0 partials [g][c][p]
    ull*   pexB = W0d + PEXB_OFF;              // cells 1/2 partials
    float* sred  = (float*)(W0d + ULL_TOT);    // 96
    float* scomb = sred + 96;                  // 48
    float* p0    = scomb + 48;                 // [6][8]
    float* pm    = p0 + 48;                    // [6][8]

    const int tid   = threadIdx.x;
    const int p     = tid & 63;      // pair within half
    const int g     = tid >> 6;      // k-group (owner of cell g if g<3)
    const int cg    = blockIdx.x >> 1;
    const int b     = blockIdx.x & 1;
    const int jbase = cg * HC_;
    const int be    = b * 128 + 2 * p;   // batch element base

    // Stage duplicated weights + params
    for (int idx = tid; idx < HC_ * 512; idx += NT_) {
        int c = idx >> 9, k = idx & 511;
        float w0 = W0[(size_t)(jbase + c) * D_ + k];
        float wm = Wm[(size_t)(jbase + c) * H_ + k];
        W0d[idx] = pk2(w0, w0);
        Wmd[idx] = pk2(wm, wm);
    }
    if (tid < HC_) {
        int j = jbase + tid;
        p0[0 * 8 + tid] = b0[j];  p0[1 * 8 + tid] = u0[j];
        p0[2 * 8 + tid] = g10[j]; p0[3 * 8 + tid] = be10[j];
        p0[4 * 8 + tid] = g20[j]; p0[5 * 8 + tid] = be20[j];
        pm[0 * 8 + tid] = bm[j];  pm[1 * 8 + tid] = um[j];
        pm[2 * 8 + tid] = g1m[j]; pm[3 * 8 + tid] = be1m[j];
        pm[4 * 8 + tid] = g2m[j]; pm[5 * 8 + tid] = be2m[j];
    }
    // Zero states + counters (per-launch; graph replays)
    for (int i = tid; i < 1024; i += NT_) {
        size_t o = (size_t)blockIdx.x * 1024 + i;
        __stcg(&d_h0 [0][o], 0.f); __stcg(&d_h0 [1][o], 0.f);
        __stcg(&d_hm0[0][o], 0.f); __stcg(&d_hm0[1][o], 0.f);
        __stcg(&d_hm1[o], 0.f);
    }
    if (blockIdx.x == 0 && tid < CG_) d_pcnt[tid] = 0u;
    __syncthreads();
    gsync();

    // ---- wavefront: step s computes L0(t=s), L1(s-1), L2(s-2) ----
    for (int s = 0; s < NS_; s++) {
        const int rd = (s + 1) & 1;
        const int wr = s & 1;
        const int tt = (s < T_) ? s : (T_ - 1);

        // ======== pass 1: cell 0 GEMM (x @ W0^T), park partials in pexA ====
        {
            const float* in0 = d_xT + (size_t)tt * D_ * B_ + (size_t)(g * KG_) * B_ + be;
            ull acc0[HC_];
            #pragma unroll
            for (int c = 0; c < HC_; c++) acc0[c] = 0ull;
            ull ac[4];
            #pragma unroll
            for (int j = 0; j < 4; j++) ac[j] = ldcg64(in0 + (size_t)j * B_);
            #pragma unroll 2
            for (int kk = 0; kk < KG_; kk += 4) {
                ull an[4];
                if (kk + 4 < KG_) {
                    #pragma unroll
                    for (int j = 0; j < 4; j++) an[j] = ldcg64(in0 + (size_t)(kk + 4 + j) * B_);
                }
                #pragma unroll
                for (int c = 0; c < HC_; c++) {
                    const ulonglong2* wp = (const ulonglong2*)(W0d + c * 512 + g * KG_ + kk);
                    ulonglong2 w0 = wp[0], w1 = wp[1];
                    fma2(acc0[c], ac[0], w0.x);
                    fma2(acc0[c], ac[1], w0.y);
                    fma2(acc0[c], ac[2], w1.x);
                    fma2(acc0[c], ac[3], w1.y);
                }
                #pragma unroll
                for (int j = 0; j < 4; j++) ac[j] = an[j];
            }
            #pragma unroll
            for (int c = 0; c < HC_; c++) pexA[(g * HC_ + c) * PP_ + p] = acc0[c];
        }

        // ======== pass 2: cells 1 & 2 GEMM (shared Wm loads) ==============
        ull acc1[HC_], acc2[HC_];
        {
            const float* in1 = d_h0 [rd] + (size_t)(g * KG_) * B_ + be;
            const float* in2 = d_hm0[rd] + (size_t)(g * KG_) * B_ + be;
            #pragma unroll
            for (int c = 0; c < HC_; c++) { acc1[c] = 0ull; acc2[c] = 0ull; }
            ull a1c[4], a2c[4];
            #pragma unroll
            for (int j = 0; j < 4; j++) {
                a1c[j] = ldcg64(in1 + (size_t)j * B_);
                a2c[j] = ldcg64(in2 + (size_t)j * B_);
            }
            #pragma unroll 2
            for (int kk = 0; kk < KG_; kk += 4) {
                ull a1n[4], a2n[4];
                if (kk + 4 < KG_) {
                    #pragma unroll
                    for (int j = 0; j < 4; j++) {
                        a1n[j] = ldcg64(in1 + (size_t)(kk + 4 + j) * B_);
                        a2n[j] = ldcg64(in2 + (size_t)(kk + 4 + j) * B_);
                    }
                }
                #pragma unroll
                for (int c = 0; c < HC_; c++) {
                    const ulonglong2* wp = (const ulonglong2*)(Wmd + c * 512 + g * KG_ + kk);
                    ulonglong2 w0 = wp[0], w1 = wp[1];
                    fma2(acc1[c], a1c[0], w0.x);
                    fma2(acc1[c], a1c[1], w0.y);
                    fma2(acc1[c], a1c[2], w1.x);
                    fma2(acc1[c], a1c[3], w1.y);
                    fma2(acc2[c], a2c[0], w0.x);
                    fma2(acc2[c], a2c[1], w0.y);
                    fma2(acc2[c], a2c[2], w1.x);
                    fma2(acc2[c], a2c[3], w1.y);
                }
                #pragma unroll
                for (int j = 0; j < 4; j++) { a1c[j] = a1n[j]; a2c[j] = a2n[j]; }
            }
        }

        // ======== k-partial reduction: owners build z ======================
        float zx[HC_], zy[HC_];
        #pragma unroll
        for (int c = 0; c < HC_; c++) pexB[(g * HC_ + c) * PP_ + p] = acc1[c];
        __syncthreads();   // pexA + pexB(cell1) visible

        if (g == 0 || g == 1) {
            const ull* px = (g == 0) ? pexA : pexB;
            const float* prm = (g == 0) ? p0 : pm;
            #pragma unroll
            for (int c = 0; c < HC_; c++) {
                float ax = prm[0 * 8 + c], ay = ax;
                #pragma unroll
                for (int gg = 0; gg < NKG_; gg++) {
                    float bx, by; upk2(bx, by, px[(gg * HC_ + c) * PP_ + p]);
                    ax += bx; ay += by;
                }
                zx[c] = ax; zy[c] = ay;
            }
        }
        __syncthreads();   // cell1 sums read before pexB overwrite
        #pragma unroll
        for (int c = 0; c < HC_; c++) pexB[(g * HC_ + c) * PP_ + p] = acc2[c];
        __syncthreads();
        if (g == 2) {
            #pragma unroll
            for (int c = 0; c < HC_; c++) {
                float ax = pm[0 * 8 + c], ay = ax;
                #pragma unroll
                for (int gg = 0; gg < NKG_; gg++) {
                    float bx, by; upk2(bx, by, pexB[(gg * HC_ + c) * PP_ + p]);
                    ax += bx; ay += by;
                }
                zx[c] = ax; zy[c] = ay;
            }
        }

        // ======== BN1: local stats -> partner exchange ====================
        if (g < 3) {
            float v16[16];
            #pragma unroll
            for (int c = 0; c < HC_; c++) {
                v16[2 * c]     = zx[c] + zy[c];
                v16[2 * c + 1] = zx[c] * zx[c] + zy[c] * zy[c];
            }
            #pragma unroll
            for (int off = 16; off > 0; off >>= 1) {
                #pragma unroll
                for (int q = 0; q < 16; q++) v16[q] += __shfl_down_sync(0xffffffffu, v16[q], off);
            }
            if ((tid & 31) == 0) {
                int w = tid >> 5;
                #pragma unroll
                for (int q = 0; q < 16; q++) sred[w * 16 + q] = v16[q];
            }
        }
        __syncthreads();
        stats_exchange(0, 4u * s + 2u, cg, b, sred, scomb);

        // ======== BN1 apply + recurrence + relu ===========================
        float yx[HC_], yy[HC_];
        if (g < 3) {
            const float* prm = (g == 0) ? p0 : pm;
            const float* hb = (g == 0) ? d_h0[rd] : (g == 1) ? d_hm0[rd] : d_hm1;
            #pragma unroll
            for (int c = 0; c < HC_; c++) {
                float m   = scomb[g * 16 + 2 * c] * (1.f / B_);
                float var = scomb[g * 16 + 2 * c + 1] * (1.f / B_) - m * m;
                float rs  = rsqrtf(var + EPS_);
                float g1 = prm[2 * 8 + c], be1 = prm[3 * 8 + c], u = prm[1 * 8 + c];
                float hx = 0.f, hy = 0.f;
                if (s != g) {
                    ull hv = ldcg64(&hb[(size_t)(jbase + c) * B_ + be]);
                    upk2(hx, hy, hv);
                }
                yx[c] = fmaxf(fmaf(hx, u, (zx[c] - m) * rs * g1 + be1), 0.f);
                yy[c] = fmaxf(fmaf(hy, u, (zy[c] - m) * rs * g1 + be1), 0.f);
            }
            // BN2 local stats
            float v16[16];
            #pragma unroll
            for (int c = 0; c < HC_; c++) {
                v16[2 * c]     = yx[c] + yy[c];
                v16[2 * c + 1] = yx[c] * yx[c] + yy[c] * yy[c];
            }
            #pragma unroll
            for (int off = 16; off > 0; off >>= 1) {
                #pragma unroll
                for (int q = 0; q < 16; q++) v16[q] += __shfl_down_sync(0xffffffffu, v16[q], off);
            }
            if ((tid & 31) == 0) {
                int w = tid >> 5;
                #pragma unroll
                for (int q = 0; q < 16; q++) sred[w * 16 + q] = v16[q];
            }
        }
        __syncthreads();
        stats_exchange(1, 4u * s + 4u, cg, b, sred, scomb);

        // ======== BN2 apply + publish state ================================
        const bool act = (g == 0) ? (s < T_)
                       : (g == 1) ? (s >= 1 && s <= T_)
                       : (g == 2) ? (s >= 2) : false;
        if (act) {
            const float* prm = (g == 0) ? p0 : pm;
            float* ob = (g == 0) ? d_h0[wr] : (g == 1) ? d_hm0[wr] : d_hm1;
            #pragma unroll
            for (int c = 0; c < HC_; c++) {
                float m   = scomb[g * 16 + 2 * c] * (1.f / B_);
                float var = scomb[g * 16 + 2 * c + 1] * (1.f / B_) - m * m;
                float rs  = rsqrtf(var + EPS_);
                float g2 = prm[4 * 8 + c], be2 = prm[5 * 8 + c];
                float ox = (yx[c] - m) * rs * g2 + be2;
                float oy = (yy[c] - m) * rs * g2 + be2;
                __stcg((ull*)&ob[(size_t)(jbase + c) * B_ + be], pk2(ox, oy));
            }
        }

        gsync();
    }

    // ---- head: logits + log_softmax (2 batch rows per CTA) ----
    float* hrow = (float*)pexA;
    for (int rr = 0; rr < 2; rr++) {
        int r = blockIdx.x * 2 + rr;
        __syncthreads();
        for (int j = tid; j < H_; j += NT_) hrow[j] = __ldcg(&d_hm1[(size_t)j * B_ + r]);
        __syncthreads();

        float acc = -INFINITY;
        if (tid < O_) {
            acc = bfc[tid];
            const float4* wrow = (const float4*)(Wfc + (size_t)tid * H_);
            #pragma unroll 4
            for (int j4 = 0; j4 < H_ / 4; j4++) {
                float4 w = wrow[j4];
                acc = fmaf(hrow[4 * j4 + 0], w.x, acc);
                acc = fmaf(hrow[4 * j4 + 1], w.y, acc);
                acc = fmaf(hrow[4 * j4 + 2], w.z, acc);
                acc = fmaf(hrow[4 * j4 + 3], w.w, acc);
            }
        }
        float mx = block_allreduce_max(acc, sred);
        float e  = (tid < O_) ? expf(acc - mx) : 0.f;
        float se = block_allreduce_sum(e, sred);
        if (tid < O_) out[(size_t)r * O_ + tid] = acc - mx - logf(se);
    }
}

// ---------------- harness entry ----------------
extern "C" void kernel_launch(void* const* d_in, const int* in_sizes, int n_in,
                              void* d_out, int out_size) {
    (void)in_sizes; (void)n_in; (void)out_size;
    const float* x    = (const float*)d_in[0];
    const float* W0   = (const float*)d_in[1];
    const float* b0   = (const float*)d_in[2];
    const float* u0   = (const float*)d_in[3];
    const float* g10  = (const float*)d_in[4];
    const float* be10 = (const float*)d_in[5];
    const float* g20  = (const float*)d_in[6];
    const float* be20 = (const float*)d_in[7];
    const float* Wm   = (const float*)d_in[8];
    const float* bm   = (const float*)d_in[9];
    const float* um   = (const float*)d_in[10];
    const float* g1m  = (const float*)d_in[11];
    const float* be1m = (const float*)d_in[12];
    const float* g2m  = (const float*)d_in[13];
    const float* be2m = (const float*)d_in[14];
    const float* Wfc  = (const float*)d_in[15];
    const float* bfc  = (const float*)d_in[16];
    float* out = (float*)d_out;

    static int attr_set = 0;
    if (!attr_set) {
        cudaFuncSetAttribute(rnn_kernel,
                             cudaFuncAttributeMaxDynamicSharedMemorySize, SMEM_BYTES);
        attr_set = 1;
    }

    transpose_kernel<<<dim3(T_, D_ / 32, B_ / 32), dim3(32, 32)>>>(x);
    rnn_kernel<<<G_, NT_, SMEM_BYTES>>>(W0, b0, u0, g10, be10, g20, be20,
                                        Wm, bm, um, g1m, be1m, g2m, be2m,
                                        Wfc, bfc, out);
}